// round 7
// baseline (speedup 1.0000x reference)
#include <cuda_runtime.h>
#include <cstdint>

#define NN 50000
#define EE 800000
#define ZB 256          // zeroing blocks in prep kernel
#define NB 782          // node blocks per type: ceil(50000/64)
#define EGB 6250        // edge blocks per relation (128 edges/block)

typedef unsigned long long u64;

// ---------------- scratch (device globals; no allocation allowed) ----------------
__device__ __align__(16) float g_sq_a[NN * 2];
__device__ __align__(16) float g_sk_a[NN * 2];
__device__ __align__(16) float g_sq_b[NN * 2];
__device__ __align__(16) float g_sk_b[NN * 2];
__device__ __align__(16) float g_v1[NN * 64];     // v_a + rel1 (natural col order)
__device__ __align__(16) float g_v2[NN * 64];     // v_b + rel2
__device__ __align__(16) float g_agg1[NN * 64];   // Σ ex*(v+rel+eb), dst = b
__device__ __align__(16) float g_agg2[NN * 64];   // dst = a
__device__ __align__(16) float g_den1[NN * 2];    // Σ ex
__device__ __align__(16) float g_den2[NN * 2];

// ---------------- helpers ----------------
__device__ __forceinline__ float tanh_fast(float x) {
    float y;
    asm("tanh.approx.f32 %0, %1;" : "=f"(y) : "f"(x));
    return y;
}
__device__ __forceinline__ u64 pack2(float lo, float hi) {
    u64 r;
    asm("mov.b64 %0, {%1, %2};" : "=l"(r) : "f"(lo), "f"(hi));
    return r;
}
__device__ __forceinline__ void unpack2(u64 v, float& lo, float& hi) {
    asm("mov.b64 {%0, %1}, %2;" : "=f"(lo), "=f"(hi) : "l"(v));
}
__device__ __forceinline__ u64 fma2(u64 a, u64 b, u64 c) {
    u64 d;
    asm("fma.rn.f32x2 %0, %1, %2, %3;" : "=l"(d) : "l"(a), "l"(b), "l"(c));
    return d;
}
__device__ __forceinline__ void red4(float* p, float a, float b, float c, float d) {
    asm volatile("red.global.add.v4.f32 [%0], {%1,%2,%3,%4};"
                 :: "l"(p), "f"(a), "f"(b), "f"(c), "f"(d) : "memory");
}
__device__ __forceinline__ void red2(float* p, float a, float b) {
    asm volatile("red.global.add.v2.f32 [%0], {%1,%2};"
                 :: "l"(p), "f"(a), "f"(b) : "memory");
}

// ---------------- prep: zero scratch + fused-QKV node precompute ----------------
// 512 threads/block, 64 nodes/block; thread tile = 2 nodes x 4 cols x 3 matrices (f32x2)
// dynamic smem: xs[64*65] | Wq[4096] | Wk[4096] | Wv[4096] | emb[64] | rel[64] | a[64]
#define PREP_SMEM ((4160 + 3 * 4096 + 192) * 4)

__global__ void __launch_bounds__(512) prep_kernel(
    const float* __restrict__ x_a, const float* __restrict__ Wq_a,
    const float* __restrict__ Wk_a, const float* __restrict__ Wv_a,
    const float* __restrict__ x_b, const float* __restrict__ Wq_b,
    const float* __restrict__ Wk_b, const float* __restrict__ Wv_b,
    const float* __restrict__ emb_a, const float* __restrict__ emb_b,
    const float* __restrict__ rel1, const float* __restrict__ rel2,
    const float* __restrict__ a_attn)
{
    int b = blockIdx.x;
    int tid = threadIdx.x;

    if (b < ZB) {
        const float4 z = make_float4(0.f, 0.f, 0.f, 0.f);
        int i = b * 512 + tid;
        const int S = ZB * 512;
        for (int k = i; k < NN * 16; k += S) { ((float4*)g_agg1)[k] = z; ((float4*)g_agg2)[k] = z; }
        for (int k = i; k < NN / 2;  k += S) { ((float4*)g_den1)[k] = z; ((float4*)g_den2)[k] = z; }
        return;
    }
    b -= ZB;
    int type = (b >= NB) ? 1 : 0;
    if (type) b -= NB;

    const float* x   = type ? x_b  : x_a;
    const float* Wqg = type ? Wq_b : Wq_a;
    const float* Wkg = type ? Wk_b : Wk_a;
    const float* Wvg = type ? Wv_b : Wv_a;
    const float* emb = type ? emb_b : emb_a;
    const float* rel = type ? rel2 : rel1;
    float* sq   = type ? g_sq_b : g_sq_a;
    float* sk   = type ? g_sk_b : g_sk_a;
    float* vout = type ? g_v2   : g_v1;

    extern __shared__ float sm[];
    float* xs   = sm;              // 64 x 65
    float* Wq   = sm + 4160;
    float* Wk   = Wq + 4096;
    float* Wv   = Wk + 4096;
    float* embS = Wv + 4096;
    float* relS = embS + 64;
    float* aS   = relS + 64;

    int nb = b * 64;

    for (int i = tid; i < 4096; i += 512) {
        int rr = i >> 6, cc = i & 63;
        int n2 = nb + rr;
        xs[rr * 65 + cc] = (n2 < NN) ? __ldg(x + n2 * 64 + cc) : 0.f;
        Wq[i] = __ldg(Wqg + i);
        Wk[i] = __ldg(Wkg + i);
        Wv[i] = __ldg(Wvg + i);
    }
    if (tid < 64) { embS[tid] = emb[tid]; relS[tid] = rel[tid]; aS[tid] = a_attn[tid]; }
    __syncthreads();

    int g = tid >> 4, cg = tid & 15, c0 = cg * 4;   // g: node pair 0..31

    const ulonglong2* WqV = (const ulonglong2*)Wq;  // row j = 16 ulonglong2
    const ulonglong2* WkV = (const ulonglong2*)Wk;
    const ulonglong2* WvV = (const ulonglong2*)Wv;

    // accumulators: [matrix][node][colpair]; zero bits == {+0.f,+0.f}
    u64 q0a = 0, q0b = 0, q1a = 0, q1b = 0;
    u64 k0a = 0, k0b = 0, k1a = 0, k1b = 0;
    u64 v0a = 0, v0b = 0, v1a = 0, v1b = 0;

#pragma unroll 8
    for (int j = 0; j < 64; j++) {
        ulonglong2 wq = WqV[j * 16 + cg];
        ulonglong2 wk = WkV[j * 16 + cg];
        ulonglong2 wv = WvV[j * 16 + cg];
        float x0 = xs[(g * 2 + 0) * 65 + j];
        float x1 = xs[(g * 2 + 1) * 65 + j];
        u64 x02 = pack2(x0, x0);
        u64 x12 = pack2(x1, x1);
        q0a = fma2(x02, wq.x, q0a); q0b = fma2(x02, wq.y, q0b);
        q1a = fma2(x12, wq.x, q1a); q1b = fma2(x12, wq.y, q1b);
        k0a = fma2(x02, wk.x, k0a); k0b = fma2(x02, wk.y, k0b);
        k1a = fma2(x12, wk.x, k1a); k1b = fma2(x12, wk.y, k1b);
        v0a = fma2(x02, wv.x, v0a); v0b = fma2(x02, wv.y, v0b);
        v1a = fma2(x12, wv.x, v1a); v1b = fma2(x12, wv.y, v1b);
    }

    float aq[8], ak[8], av[8];
    unpack2(q0a, aq[0], aq[1]); unpack2(q0b, aq[2], aq[3]);
    unpack2(q1a, aq[4], aq[5]); unpack2(q1b, aq[6], aq[7]);
    unpack2(k0a, ak[0], ak[1]); unpack2(k0b, ak[2], ak[3]);
    unpack2(k1a, ak[4], ak[5]); unpack2(k1b, ak[6], ak[7]);
    unpack2(v0a, av[0], av[1]); unpack2(v0b, av[2], av[3]);
    unpack2(v1a, av[4], av[5]); unpack2(v1b, av[6], av[7]);

    int n0 = nb + g * 2;

    // ---- scores: reduce across the 8 col-groups of each head (16-lane halves) ----
    float pq[2], pk[2];
#pragma unroll
    for (int r = 0; r < 2; r++) {
        float sQ = 0.f, sK = 0.f;
#pragma unroll
        for (int k = 0; k < 4; k++) {
            int c = c0 + k;
            sQ += tanh_fast(aq[r * 4 + k] + embS[c]) * aS[c & 31];
            sK += tanh_fast(ak[r * 4 + k] + embS[c]) * aS[32 + (c & 31)];
        }
        pq[r] = sQ; pk[r] = sK;
    }
#pragma unroll
    for (int m = 1; m < 8; m <<= 1) {
#pragma unroll
        for (int r = 0; r < 2; r++) {
            pq[r] += __shfl_xor_sync(0xffffffffu, pq[r], m);
            pk[r] += __shfl_xor_sync(0xffffffffu, pk[r], m);
        }
    }
    if ((cg & 7) == 0) {
        int h = cg >> 3;
#pragma unroll
        for (int r = 0; r < 2; r++) {
            int n = n0 + r;
            if (n < NN) { sq[n * 2 + h] = pq[r]; sk[n * 2 + h] = pk[r]; }
        }
    }

    // ---- V: store (v + rel) in natural column order ----
#pragma unroll
    for (int r = 0; r < 2; r++) {
        int n = n0 + r;
        if (n < NN) {
            *(float4*)(vout + (size_t)n * 64 + c0) =
                make_float4(av[r*4+0] + relS[c0+0], av[r*4+1] + relS[c0+1],
                            av[r*4+2] + relS[c0+2], av[r*4+3] + relS[c0+3]);
        }
    }
}

// ---------------- merged edge pass: 8 threads/edge, f32x2 GEMV ----------------
// lane l owns cols {4l..4l+3} (head 0) and {32+4l..32+4l+3} (head 1)
__global__ void __launch_bounds__(256) edge_kernel(
    const float* __restrict__ ea1, const int* __restrict__ row1, const int* __restrict__ col1,
    const float* __restrict__ ea2, const int* __restrict__ row2, const int* __restrict__ col2,
    const float* __restrict__ We, const float* __restrict__ a_attn)
{
    int bb = blockIdx.x;
    int relid = (bb >= EGB) ? 1 : 0;
    if (relid) bb -= EGB;

    const float* ea  = relid ? ea2  : ea1;
    const int*   row = relid ? row2 : row1;
    const int*   col = relid ? col2 : col1;
    const float* sq  = relid ? g_sq_a : g_sq_b;   // destination-node q scalar
    const float* sk  = relid ? g_sk_b : g_sk_a;   // source-node k scalar
    const float* vsrc = relid ? g_v2 : g_v1;
    float* agg = relid ? g_agg2 : g_agg1;
    float* den = relid ? g_den2 : g_den1;

    __shared__ __align__(16) float WeS[1024];     // [16][64] natural
    __shared__ float a4S[32];
    int tid = threadIdx.x;
    for (int i = tid; i < 1024; i += 256) WeS[i] = We[i];
    if (tid < 32) a4S[tid] = a_attn[96 + tid];
    __syncthreads();

    int lane = tid & 7;
    int grp  = tid >> 3;
    const ulonglong2* WeV = (const ulonglong2*)WeS;   // row j = 16 ulonglong2

#pragma unroll 1
    for (int it = 0; it < 4; it++) {
        int e = (bb * 4 + it) * 32 + grp;
        int r = __ldg(row + e), c = __ldg(col + e);

        const float4* ea4p = (const float4*)ea + (size_t)e * 4;
        float4 A = __ldg(ea4p), B = __ldg(ea4p + 1), C = __ldg(ea4p + 2), D = __ldg(ea4p + 3);
        float ear[16] = {A.x, A.y, A.z, A.w, B.x, B.y, B.z, B.w,
                         C.x, C.y, C.z, C.w, D.x, D.y, D.z, D.w};

        u64 a01 = 0, a23 = 0, a45 = 0, a67 = 0;   // packed acc: head0 pairs, head1 pairs
#pragma unroll
        for (int j = 0; j < 16; j++) {
            u64 ev2 = pack2(ear[j], ear[j]);
            ulonglong2 w0 = WeV[j * 16 + lane];        // cols 4l..4l+3
            ulonglong2 w1 = WeV[j * 16 + 8 + lane];    // cols 32+4l..32+4l+3
            a01 = fma2(ev2, w0.x, a01);
            a23 = fma2(ev2, w0.y, a23);
            a45 = fma2(ev2, w1.x, a45);
            a67 = fma2(ev2, w1.y, a67);
        }
        float acc[8];
        unpack2(a01, acc[0], acc[1]); unpack2(a23, acc[2], acc[3]);
        unpack2(a45, acc[4], acc[5]); unpack2(a67, acc[6], acc[7]);

        // score: head0 cols 4l+t (a idx 4l+t), head1 cols 32+4l+t (a idx 4l+t)
        float se0 = 0.f, se1 = 0.f;
#pragma unroll
        for (int t = 0; t < 4; t++) {
            float av = a4S[4 * lane + t];
            se0 += tanh_fast(acc[t])     * av;
            se1 += tanh_fast(acc[4 + t]) * av;
        }
#pragma unroll
        for (int m = 1; m < 8; m <<= 1) {
            se0 += __shfl_xor_sync(0xffffffffu, se0, m);
            se1 += __shfl_xor_sync(0xffffffffu, se1, m);
        }

        float2 sqv = __ldg((const float2*)sq + c);
        float2 skv = __ldg((const float2*)sk + r);
        float ex0 = __expf(sqv.x + skv.x + se0);
        float ex1 = __expf(sqv.y + skv.y + se1);

        if (lane == 0) red2(den + c * 2, ex0, ex1);

        // v gather: natural layout, contiguous per 8-lane group
        const float4* vp = (const float4*)vsrc + (size_t)r * 16;
        float4 v0 = __ldg(vp + lane);              // cols 4l..4l+3
        float4 v1 = __ldg(vp + 8 + lane);          // cols 32+4l..

        float* ap = agg + (size_t)c * 64;
        red4(ap + 4 * lane,
             ex0 * (v0.x + acc[0]), ex0 * (v0.y + acc[1]),
             ex0 * (v0.z + acc[2]), ex0 * (v0.w + acc[3]));
        red4(ap + 32 + 4 * lane,
             ex1 * (v1.x + acc[4]), ex1 * (v1.y + acc[5]),
             ex1 * (v1.z + acc[6]), ex1 * (v1.w + acc[7]));
    }
}

// ---------------- final: out = (agg/den)@Wo + bo + x@Wr  (both types via grid.y) ----------------
__global__ void __launch_bounds__(256) final_kernel(
    const float* __restrict__ Wo_a, const float* __restrict__ bo_a,
    const float* __restrict__ x_a,  const float* __restrict__ Wr_a,
    const float* __restrict__ Wo_b, const float* __restrict__ bo_b,
    const float* __restrict__ x_b,  const float* __restrict__ Wr_b,
    float* __restrict__ out)
{
    int type = blockIdx.y;   // 0 = a, 1 = b
    const float* Wo = type ? Wo_b : Wo_a;
    const float* bo = type ? bo_b : bo_a;
    const float* x  = type ? x_b  : x_a;
    const float* Wr = type ? Wr_b : Wr_a;
    const float* agg = type ? g_agg1 : g_agg2;   // a's messages come from relation 2
    const float* den = type ? g_den1 : g_den2;
    float* outp = out + (size_t)type * NN * 32;

    __shared__ float afs[32][65];
    __shared__ float xs[32][65];
    __shared__ __align__(16) float WoS[64][32];
    __shared__ __align__(16) float WrS[64][32];
    __shared__ float denS[32][2];
    __shared__ float boS[32];

    int tid = threadIdx.x;
    int nb  = blockIdx.x * 32;

    if (tid < 64) {
        int n2 = nb + (tid >> 1);
        denS[tid >> 1][tid & 1] = (n2 < NN) ? den[n2 * 2 + (tid & 1)] : 0.f;
    }
    if (tid < 32) boS[tid] = bo[tid];
    __syncthreads();

    for (int i = tid; i < 2048; i += 256) {
        int s = i >> 5, o = i & 31;
        WoS[s][o] = Wo[s * 32 + o];
        WrS[s][o] = Wr[s * 32 + o];
        int n2 = nb + (i >> 6), c2 = i & 63;
        float d = denS[i >> 6][c2 >> 5];
        float av = (n2 < NN) ? agg[(size_t)n2 * 64 + c2] : 0.f;
        afs[i >> 6][c2] = (d > 0.f) ? av / d : 0.f;
        xs[i >> 6][c2]  = (n2 < NN) ? x[(size_t)n2 * 64 + c2] : 0.f;
    }
    __syncthreads();

    int nl = tid >> 3, p = tid & 7;
    int n = nb + nl;

    u64 o01 = pack2(boS[p * 4 + 0], boS[p * 4 + 1]);
    u64 o23 = pack2(boS[p * 4 + 2], boS[p * 4 + 3]);
#pragma unroll 8
    for (int k = 0; k < 64; k++) {
        float a  = afs[nl][k];
        float xv = xs[nl][k];
        u64 a2 = pack2(a, a);
        u64 x2 = pack2(xv, xv);
        ulonglong2 wo = *(const ulonglong2*)&WoS[k][p * 4];
        ulonglong2 wr = *(const ulonglong2*)&WrS[k][p * 4];
        o01 = fma2(a2, wo.x, o01); o23 = fma2(a2, wo.y, o23);
        o01 = fma2(x2, wr.x, o01); o23 = fma2(x2, wr.y, o23);
    }
    if (n < NN) {
        float o[4];
        unpack2(o01, o[0], o[1]); unpack2(o23, o[2], o[3]);
        float4* op = (float4*)(outp + (size_t)n * 32 + p * 4);
        op[0] = make_float4(o[0], o[1], o[2], o[3]);
    }
}

// ---------------- launch ----------------
extern "C" void kernel_launch(void* const* d_in, const int* in_sizes, int n_in,
                              void* d_out, int out_size)
{
    const float* x_a    = (const float*)d_in[0];
    const float* x_b    = (const float*)d_in[1];
    const float* ea1    = (const float*)d_in[2];
    const float* ea2    = (const float*)d_in[3];
    const float* Wq_a   = (const float*)d_in[4];
    const float* Wk_a   = (const float*)d_in[5];
    const float* Wv_a   = (const float*)d_in[6];
    const float* Wq_b   = (const float*)d_in[7];
    const float* Wk_b   = (const float*)d_in[8];
    const float* Wv_b   = (const float*)d_in[9];
    const float* emb_a  = (const float*)d_in[10];
    const float* emb_b  = (const float*)d_in[11];
    const float* rel1   = (const float*)d_in[12];
    const float* rel2   = (const float*)d_in[13];
    const float* We     = (const float*)d_in[14];
    const float* a_attn = (const float*)d_in[15];
    const float* Wo_a   = (const float*)d_in[16];
    const float* bo_a   = (const float*)d_in[17];
    const float* Wo_b   = (const float*)d_in[18];
    const float* bo_b   = (const float*)d_in[19];
    const float* Wr_a   = (const float*)d_in[20];
    const float* Wr_b   = (const float*)d_in[21];
    const int*   row1   = (const int*)d_in[22];
    const int*   col1   = (const int*)d_in[23];
    const int*   row2   = (const int*)d_in[24];
    const int*   col2   = (const int*)d_in[25];
    float* out = (float*)d_out;

    cudaFuncSetAttribute(prep_kernel, cudaFuncAttributeMaxDynamicSharedMemorySize, PREP_SMEM);

    prep_kernel<<<ZB + 2 * NB, 512, PREP_SMEM>>>(x_a, Wq_a, Wk_a, Wv_a,
                                                 x_b, Wq_b, Wk_b, Wv_b,
                                                 emb_a, emb_b, rel1, rel2, a_attn);

    edge_kernel<<<2 * EGB, 256>>>(ea1, row1, col1, ea2, row2, col2, We, a_attn);

    dim3 fg((NN + 31) / 32, 2);
    final_kernel<<<fg, 256>>>(Wo_a, bo_a, x_a, Wr_a,
                              Wo_b, bo_b, x_b, Wr_b, out);
}